// round 1
// baseline (speedup 1.0000x reference)
#include <cuda_runtime.h>
#include <math_constants.h>

#define PRE   1024
#define POSTN 1024
#define BATCH 32
#define NB    2048
#define NTH   256
#define EPT   4   // elements per thread (NTH*EPT == PRE)

// Transposed copies of delays/weights: [post][pre], coalesced for the main kernel.
__device__ float g_dT[POSTN * PRE];
__device__ float g_wT[POSTN * PRE];

// ---------------------------------------------------------------------------
// Transpose weights [PRE][POST] and delays [PRE][POST] -> [POST][PRE]
// ---------------------------------------------------------------------------
__global__ void transpose_kernel(const float* __restrict__ W,
                                 const float* __restrict__ D)
{
    __shared__ float tw[32][33];
    __shared__ float td[32][33];
    int x  = blockIdx.x * 32 + threadIdx.x;   // post (input col)
    int y0 = blockIdx.y * 32;                 // pre  (input row base)
#pragma unroll
    for (int j = 0; j < 32; j += 8) {
        tw[threadIdx.y + j][threadIdx.x] = W[(size_t)(y0 + threadIdx.y + j) * POSTN + x];
        td[threadIdx.y + j][threadIdx.x] = D[(size_t)(y0 + threadIdx.y + j) * POSTN + x];
    }
    __syncthreads();
    int xo  = blockIdx.y * 32 + threadIdx.x;  // pre (output col)
    int yo0 = blockIdx.x * 32;                // post (output row base)
#pragma unroll
    for (int j = 0; j < 32; j += 8) {
        g_wT[(size_t)(yo0 + threadIdx.y + j) * PRE + xo] = tw[threadIdx.x][threadIdx.y + j];
        g_dT[(size_t)(yo0 + threadIdx.y + j) * PRE + xo] = td[threadIdx.x][threadIdx.y + j];
    }
}

// ---------------------------------------------------------------------------
// Main kernel: one block per (batch, post) problem.
//  1) compute t_i = spike[b][i] + delay[i][post], w_i = weight[i][post]
//  2) bucket (counting) sort by t (2048 value-uniform buckets over [0,2))
//  3) tiny insertion sorts inside buckets (tie-break on original index -> deterministic)
//  4) inclusive scans of w and w*t in sorted order
//  5) candidate eval: tmp = (theta + cumwt)/cumw (cumw>0), valid in [t_k, t_{k+1}]
//  6) min-reduce -> out[b][post]
// ---------------------------------------------------------------------------
__global__ __launch_bounds__(NTH)
void equaltime_kernel(const float* __restrict__ spikes,
                      const float* __restrict__ thresholds,
                      float* __restrict__ out)
{
    __shared__ int   offs[NB + 1];
    __shared__ float t_s[PRE];
    __shared__ float w_s[PRE];
    __shared__ int   i_s[PRE];
    __shared__ int   siwarp[8];
    __shared__ float swsum[8];
    __shared__ float swtsum[8];
    __shared__ float sred[8];

    const int tid  = threadIdx.x;
    const int bid  = blockIdx.x;
    const int post = bid >> 5;   // 32 consecutive blocks share one post column (L2 reuse)
    const int b    = bid & 31;

    const float* dT = g_dT + (size_t)post * PRE;
    const float* wT = g_wT + (size_t)post * PRE;
    const float* sp = spikes + (size_t)b * PRE;

    // zero bucket counters
    for (int j = tid; j <= NB; j += NTH) offs[j] = 0;

    // load + compute event times, keep in registers across phases
    float tv[EPT], wv[EPT];
    int   bk[EPT];
#pragma unroll
    for (int k = 0; k < EPT; k++) {
        int i   = tid + k * NTH;
        float t = sp[i] + dT[i];
        float w = wT[i];
        tv[k] = t;
        wv[k] = w;
        int bb = (int)(t * 1024.0f);          // value-uniform bucket over [0,2)
        bb = max(0, min(bb, NB - 1));
        bk[k] = bb;
    }
    __syncthreads();

    // histogram (counts shifted by +1 so inclusive scan gives bucket starts)
#pragma unroll
    for (int k = 0; k < EPT; k++) atomicAdd(&offs[bk[k] + 1], 1);
    __syncthreads();

    // inclusive scan of offs[1..NB] (2048 ints), 8 contiguous per thread
    {
        int base = 1 + tid * 8;
        int v[8];
        int run = 0;
#pragma unroll
        for (int j = 0; j < 8; j++) { run += offs[base + j]; v[j] = run; }
        int lane = tid & 31, wid = tid >> 5;
        int x = run;
#pragma unroll
        for (int o = 1; o < 32; o <<= 1) {
            int n = __shfl_up_sync(0xffffffffu, x, o);
            if (lane >= o) x += n;
        }
        if (lane == 31) siwarp[wid] = x;
        __syncthreads();
        if (tid < 8) {
            int y = siwarp[tid];
#pragma unroll
            for (int o = 1; o < 8; o <<= 1) {
                int n = __shfl_up_sync(0x000000ffu, y, o);
                if (tid >= o) y += n;
            }
            siwarp[tid] = y;
        }
        __syncthreads();
        int excl = x - run + (wid ? siwarp[wid - 1] : 0);
#pragma unroll
        for (int j = 0; j < 8; j++) offs[base + j] = excl + v[j];
        if (tid == 0) offs[0] = 0;
    }
    __syncthreads();

    // scatter: offs[bucket] is the bucket start; post-scatter it becomes the end
#pragma unroll
    for (int k = 0; k < EPT; k++) {
        int pos  = atomicAdd(&offs[bk[k]], 1);
        t_s[pos] = tv[k];
        w_s[pos] = wv[k];
        i_s[pos] = tid + k * NTH;
    }
    __syncthreads();

    // intra-bucket insertion sort (buckets are tiny; tie-break on original idx)
    for (int j = tid; j < NB; j += NTH) {
        int lo = (j == 0) ? 0 : offs[j - 1];
        int hi = offs[j];
        for (int a = lo + 1; a < hi; a++) {
            float ta = t_s[a], wa = w_s[a];
            int   ia = i_s[a];
            int c = a;
            while (c > lo && (t_s[c - 1] > ta ||
                              (t_s[c - 1] == ta && i_s[c - 1] > ia))) {
                t_s[c] = t_s[c - 1]; w_s[c] = w_s[c - 1]; i_s[c] = i_s[c - 1];
                c--;
            }
            t_s[c] = ta; w_s[c] = wa; i_s[c] = ia;
        }
    }
    __syncthreads();

    // scans of w and w*t over sorted order (4 contiguous elems per thread)
    const int base = tid * EPT;
    float lt[EPT], lw[EPT], lcw[EPT], lcwt[EPT];
    float cw = 0.f, cwt = 0.f;
#pragma unroll
    for (int j = 0; j < EPT; j++) {
        lt[j] = t_s[base + j];
        lw[j] = w_s[base + j];
        cw  += lw[j];
        cwt += lw[j] * lt[j];
        lcw[j]  = cw;
        lcwt[j] = cwt;
    }
    int lane = tid & 31, wid = tid >> 5;
    float xw = cw, xwt = cwt;
#pragma unroll
    for (int o = 1; o < 32; o <<= 1) {
        float nw  = __shfl_up_sync(0xffffffffu, xw, o);
        float nwt = __shfl_up_sync(0xffffffffu, xwt, o);
        if (lane >= o) { xw += nw; xwt += nwt; }
    }
    if (lane == 31) { swsum[wid] = xw; swtsum[wid] = xwt; }
    __syncthreads();
    if (tid < 8) {
        float yw = swsum[tid], ywt = swtsum[tid];
#pragma unroll
        for (int o = 1; o < 8; o <<= 1) {
            float nw  = __shfl_up_sync(0x000000ffu, yw, o);
            float nwt = __shfl_up_sync(0x000000ffu, ywt, o);
            if (tid >= o) { yw += nw; ywt += nwt; }
        }
        swsum[tid] = yw; swtsum[tid] = ywt;
    }
    __syncthreads();
    float ew  = xw  - cw  + (wid ? swsum[wid - 1]  : 0.f);
    float ewt = xwt - cwt + (wid ? swtsum[wid - 1] : 0.f);

    // candidate evaluation
    const float theta = thresholds[post];
    float tnext_tail = (base + EPT < PRE) ? t_s[base + EPT] : 0.f;
    float best = CUDART_INF_F;
#pragma unroll
    for (int j = 0; j < EPT; j++) {
        int   idx = base + j;
        float CW  = ew  + lcw[j];
        float CWT = ewt + lcwt[j];
        float tk  = lt[j];
        float tn  = (j < EPT - 1) ? lt[j + 1] : tnext_tail;
        float tmp = (CW > 0.f) ? (theta + CWT) / CW : CUDART_INF_F;
        bool  bad = (tmp < tk) || ((idx < PRE - 1) && (tmp > tn));
        if (!bad) best = fminf(best, tmp);
    }

    // block min-reduce
#pragma unroll
    for (int o = 16; o > 0; o >>= 1)
        best = fminf(best, __shfl_xor_sync(0xffffffffu, best, o));
    if (lane == 0) sred[wid] = best;
    __syncthreads();
    if (tid == 0) {
        float m = sred[0];
#pragma unroll
        for (int i = 1; i < 8; i++) m = fminf(m, sred[i]);
        out[(size_t)b * POSTN + post] = m;
    }
}

// ---------------------------------------------------------------------------
extern "C" void kernel_launch(void* const* d_in, const int* in_sizes, int n_in,
                              void* d_out, int out_size)
{
    const float* spikes  = (const float*)d_in[0];  // [32, 1024]
    const float* weights = (const float*)d_in[1];  // [1024, 1024]
    const float* delays  = (const float*)d_in[2];  // [1024, 1024]
    const float* thr     = (const float*)d_in[3];  // [1024]
    float* out = (float*)d_out;                    // [32, 1024]

    dim3 tb(32, 8);
    dim3 tg(POSTN / 32, PRE / 32);
    transpose_kernel<<<tg, tb>>>(weights, delays);

    equaltime_kernel<<<BATCH * POSTN, NTH>>>(spikes, thr, out);
}